// round 11
// baseline (speedup 1.0000x reference)
#include <cuda_runtime.h>
#include <cstdint>

// SpikeFP32Multiplier v7 — two-phase split for unidirectional DRAM streams.
// Phase 1: read A,B (512MB, evict-first), ballot-pack, IEEE multiply, write
//          packed product words (8MB) to L2-resident scratch. ~pure-READ DRAM.
// Phase 2: read packed words (8MB, L2 hits), expand to spike bits, write
//          output (256MB, evict-first). ~pure-WRITE DRAM.
// Mechanism: removes DRAM R/W turnaround that capped the fused kernel at
// ~85% DRAM active (6.8 TB/s) across all schedule variants (R3-R8).

static constexpr int ELEMS_PER_WARP = 8;
static constexpr int MAX_ELEMS = 2048 * 1024;

__device__ uint32_t g_packed[MAX_ELEMS];   // 8 MB scratch (static, rule-compliant)

__global__ void spike_mul_pack(const uint32_t* __restrict__ A,
                               const uint32_t* __restrict__ B,
                               int n_elems) {
    const int lane = threadIdx.x & 31;
    const int warp = (blockIdx.x * blockDim.x + threadIdx.x) >> 5;
    const int e0 = warp * ELEMS_PER_WARP;
    if (e0 >= n_elems) return;

    const int w = 31 - lane;  // memory word owned by this lane

    // Read burst: 16 outstanding LDG.32 per lane, evict-first (no reuse).
    uint32_t a[ELEMS_PER_WARP], b[ELEMS_PER_WARP];
#pragma unroll
    for (int i = 0; i < ELEMS_PER_WARP; ++i) {
        size_t off = (size_t)(e0 + i) * 32 + w;
        a[i] = __ldcs(A + off);
        b[i] = __ldcs(B + off);
    }

    uint32_t myword = 0;
#pragma unroll
    for (int i = 0; i < ELEMS_PER_WARP; ++i) {
        // ballot bit l = (word 31-l != 0) = IEEE bit l. Direct pack.
        uint32_t ua = __ballot_sync(0xFFFFFFFFu, a[i] != 0u);
        uint32_t ub = __ballot_sync(0xFFFFFFFFu, b[i] != 0u);
        // IEEE-754 fp32 multiply, RNE, subnormal-aware (no -ftz).
        uint32_t up = __float_as_uint(__uint_as_float(ua) * __uint_as_float(ub));
        if (lane == i) myword = up;   // lane i keeps element e0+i's product
    }

    // Lanes 0..7 store 8 contiguous packed words (default policy: L2-resident).
    if (lane < ELEMS_PER_WARP) g_packed[e0 + lane] = myword;
}

__global__ void spike_mul_expand(uint32_t* __restrict__ out, int n_elems) {
    const int lane = threadIdx.x & 31;
    const int warp = (blockIdx.x * blockDim.x + threadIdx.x) >> 5;
    const int e0 = warp * ELEMS_PER_WARP;
    if (e0 >= n_elems) return;

    const int w = 31 - lane;

    // Packed words: uniform address per warp -> LDG broadcast, L2 hits (8MB).
    uint32_t v[ELEMS_PER_WARP];
#pragma unroll
    for (int i = 0; i < ELEMS_PER_WARP; ++i) {
        uint32_t up = g_packed[e0 + i];
        v[i] = ((up >> lane) & 1u) ? 0x3F800000u : 0u;
    }

    // Write burst: evict-first streaming stores, fully coalesced.
#pragma unroll
    for (int i = 0; i < ELEMS_PER_WARP; ++i) {
        __stcs(out + (size_t)(e0 + i) * 32 + w, v[i]);
    }
}

extern "C" void kernel_launch(void* const* d_in, const int* in_sizes, int n_in,
                              void* d_out, int out_size) {
    const uint32_t* A = (const uint32_t*)d_in[0];
    const uint32_t* B = (const uint32_t*)d_in[1];
    uint32_t* out = (uint32_t*)d_out;

    int n_elems = in_sizes[0] / 32;
    if (n_elems > MAX_ELEMS) n_elems = MAX_ELEMS;  // scratch bound (shape is fixed)

    const int block = 256;  // 8 warps per block
    int warps_needed = (n_elems + ELEMS_PER_WARP - 1) / ELEMS_PER_WARP;
    int grid = (warps_needed * 32 + block - 1) / block;

    spike_mul_pack<<<grid, block>>>(A, B, n_elems);
    spike_mul_expand<<<grid, block>>>(out, n_elems);
}

// round 12
// speedup vs baseline: 1.1070x; 1.1070x over previous
#include <cuda_runtime.h>
#include <cstdint>

// SpikeFP32Multiplier — FINAL (v3 configuration; roofline-verified).
// A,B: [N, 32] float32 spike bits, MSB-first IEEE-754 fp32 layout.
// Semantics: pack 32 bits -> fp32, IEEE multiply (RNE, subnormal-aware),
// unpack 32 bits. Pure HBM stream: 768 MB irreducible traffic.
//
// Design decisions, each ncu-validated across R2-R11:
//  - Warp-cooperative: lane l owns memory word (31-l), so ballot bit l is
//    IEEE bit l directly (no __brev). One 128B line per warp mem instr
//    (fixes the R1 L1tex-wavefront bottleneck: 84.5% L1 -> 34%).
//  - ELEMS_PER_WARP=8 -> 16 outstanding LDG.32/lane (MLP=16), regs=26.
//  - __ldcs/__stcs: evict-first streaming (zero reuse through 126MB L2).
//  - One-shot oversubscribed grid (32768 CTAs): continuous CTA arrival keeps
//    DRAM queues full. Persistent grid measured 10% slower (MLP drain).
//  - Fused read+write: mixed stream sustains 4.6 TB/s read + 2.3 TB/s write
//    CONCURRENTLY; a split read-phase/write-phase design measured 11% slower
//    (pure-write stream caps at ~4.5 TB/s).
// Measured: ~112-115 us device, DRAM 85% (~6.86 TB/s aggregate) = practical
// ceiling for this 2:1 R:W stream; issue 21%, all compute pipes idle.

static constexpr int ELEMS_PER_WARP = 8;

__global__ void spike_fp32_mul_final(const uint32_t* __restrict__ A,
                                     const uint32_t* __restrict__ B,
                                     uint32_t* __restrict__ out,
                                     int n_elems) {
    const int lane = threadIdx.x & 31;
    const int warp = (blockIdx.x * blockDim.x + threadIdx.x) >> 5;
    const int e0 = warp * ELEMS_PER_WARP;
    if (e0 >= n_elems) return;

    const int w = 31 - lane;  // memory word owned by this lane

    // Read burst: 16 outstanding LDG.32 per lane.
    uint32_t a[ELEMS_PER_WARP], b[ELEMS_PER_WARP];
#pragma unroll
    for (int i = 0; i < ELEMS_PER_WARP; ++i) {
        size_t off = (size_t)(e0 + i) * 32 + w;
        a[i] = __ldcs(A + off);
        b[i] = __ldcs(B + off);
    }

#pragma unroll
    for (int i = 0; i < ELEMS_PER_WARP; ++i) {
        // ballot bit l = (word 31-l != 0) = IEEE bit l. Direct pack.
        uint32_t ua = __ballot_sync(0xFFFFFFFFu, a[i] != 0u);
        uint32_t ub = __ballot_sync(0xFFFFFFFFu, b[i] != 0u);

        // IEEE-754 fp32 multiply, RNE, subnormal-aware (no -ftz).
        float p = __uint_as_float(ua) * __uint_as_float(ub);
        uint32_t up = __float_as_uint(p);

        // Lane l emits IEEE bit l as float 1.0f/0.0f bit pattern at word 31-l.
        uint32_t val = ((up >> lane) & 1u) ? 0x3F800000u : 0u;
        __stcs(out + (size_t)(e0 + i) * 32 + w, val);
    }
}

extern "C" void kernel_launch(void* const* d_in, const int* in_sizes, int n_in,
                              void* d_out, int out_size) {
    const uint32_t* A = (const uint32_t*)d_in[0];
    const uint32_t* B = (const uint32_t*)d_in[1];
    uint32_t* out = (uint32_t*)d_out;

    int n_elems = in_sizes[0] / 32;

    const int block = 256;  // 8 warps per block
    int warps_needed = (n_elems + ELEMS_PER_WARP - 1) / ELEMS_PER_WARP;
    int grid = (warps_needed * 32 + block - 1) / block;
    spike_fp32_mul_final<<<grid, block>>>(A, B, out, n_elems);
}